// round 14
// baseline (speedup 1.0000x reference)
#include <cuda_runtime.h>
#include <cstdint>

#define NU    100000
#define NI    50000
#define NN    150000            // NU + NI
#define D     64
#define NNZ_  8000000
#define HOPS  3

// Static device scratch (per harness rules: no allocations).
__device__ int  g_cnt[NN];        // per-row edge count
__device__ int  g_start[NN];      // CSR row start
__device__ int  g_cursor[NN];     // scatter cursor
__device__ int2 g_edges[NNZ_];    // {col | keepmask<<18, val*2 bits}

// ---------------------------------------------------------------------------
// Init: out[:, 0, :] = concat(user, item); zero row-count histogram.
// ---------------------------------------------------------------------------
__global__ void init_kernel(const float* __restrict__ user,
                            const float* __restrict__ item,
                            float* __restrict__ out) {
    int t = blockIdx.x * blockDim.x + threadIdx.x;
    if (t < NN) g_cnt[t] = 0;
    const int total = NN * D / 16;          // 600,000 threads
    if (t >= total) return;
    const int base   = t * 4;
    const int userF4 = NU * D / 4;
    float4 v[4];
    #pragma unroll
    for (int i = 0; i < 4; ++i) {
        int idx = base + i;
        v[i] = (idx < userF4) ? ((const float4*)user)[idx]
                              : ((const float4*)item)[idx - userF4];
    }
    const int node = base >> 4;
    const int f4   = base & 15;
    #pragma unroll
    for (int i = 0; i < 4; ++i)
        ((float4*)out)[(size_t)node * 64 + f4 + i] = v[i];
}

// ---------------------------------------------------------------------------
// Histogram: g_cnt[rows[e]]++ — 8 independent edges per iteration (MLP).
// ---------------------------------------------------------------------------
__global__ void hist_kernel(const int* __restrict__ rows) {
    int t  = blockIdx.x * blockDim.x + threadIdx.x;
    int nt = gridDim.x * blockDim.x;
    for (int base = t; base < NNZ_; base += 8 * nt) {
        int  e[8]; bool g[8]; int r[8];
        #pragma unroll
        for (int k = 0; k < 8; ++k) { e[k] = base + k * nt; g[k] = e[k] < NNZ_; }
        #pragma unroll
        for (int k = 0; k < 8; ++k) if (g[k]) r[k] = __ldcs(rows + e[k]);
        #pragma unroll
        for (int k = 0; k < 8; ++k) if (g[k]) atomicAdd(&g_cnt[r[k]], 1);
    }
}

// ---------------------------------------------------------------------------
// Exclusive scan of g_cnt -> g_start, g_cursor. One block, 1024 threads.
// ---------------------------------------------------------------------------
__global__ void scan_kernel() {
    const int T = 1024;
    const int C = (NN + T - 1) / T;
    int t = threadIdx.x;
    int s = 0;
    for (int i = 0; i < C; ++i) {
        int r = t * C + i;
        if (r < NN) s += g_cnt[r];
    }
    int lane = t & 31, w = t >> 5;
    int v = s;
    #pragma unroll
    for (int o = 1; o < 32; o <<= 1) {
        int n = __shfl_up_sync(0xFFFFFFFFu, v, o);
        if (lane >= o) v += n;
    }
    __shared__ int ws[32];
    if (lane == 31) ws[w] = v;
    __syncthreads();
    if (w == 0) {
        int x = ws[lane];
        #pragma unroll
        for (int o = 1; o < 32; o <<= 1) {
            int n = __shfl_up_sync(0xFFFFFFFFu, x, o);
            if (lane >= o) x += n;
        }
        ws[lane] = x;
    }
    __syncthreads();
    int run = v - s + (w > 0 ? ws[w - 1] : 0);
    for (int i = 0; i < C; ++i) {
        int r = t * C + i;
        if (r < NN) {
            g_start[r]  = run;
            g_cursor[r] = run;
            run += g_cnt[r];
        }
    }
}

// ---------------------------------------------------------------------------
// Scatter edges into CSR order — 8 independent chains/thread to hide the
// cursor-atomic + scattered-store latency. Record: {col|mask<<18, val*2}.
// ---------------------------------------------------------------------------
__global__ void scatter_kernel(const int*   __restrict__ rows,
                               const int*   __restrict__ cols,
                               const float* __restrict__ vals,
                               const float* __restrict__ erand) {
    int t  = blockIdx.x * blockDim.x + threadIdx.x;
    int nt = gridDim.x * blockDim.x;
    for (int base = t; base < NNZ_; base += 8 * nt) {
        int  e[8]; bool g[8]; int r[8], p[8]; int2 rec[8];
        #pragma unroll
        for (int k = 0; k < 8; ++k) { e[k] = base + k * nt; g[k] = e[k] < NNZ_; }
        #pragma unroll
        for (int k = 0; k < 8; ++k) {
            if (g[k]) {
                int   ee = e[k];
                r[k]     = __ldcs(rows + ee);
                int   c  = __ldcs(cols + ee);
                float v  = __ldcs(vals + ee) * 2.0f;    // 1/(1-0.5)
                int m = (__ldcs(erand + ee)            >= 0.5f ? 1 : 0)
                      | (__ldcs(erand + NNZ_ + ee)     >= 0.5f ? 2 : 0)
                      | (__ldcs(erand + 2 * NNZ_ + ee) >= 0.5f ? 4 : 0);
                rec[k] = make_int2(c | (m << 18), __float_as_int(v));
            }
        }
        #pragma unroll
        for (int k = 0; k < 8; ++k)
            if (g[k]) p[k] = atomicAdd(&g_cursor[r[k]], 1);
        #pragma unroll
        for (int k = 0; k < 8; ++k)
            if (g[k]) g_edges[p[k]] = rec[k];
    }
}

// ---------------------------------------------------------------------------
// CSR SpMM + fused message dropout. HALF-WARP PER ROW:
// 16 lanes x float4 = D exactly; accumulator in registers (row owned by one
// half-warp -> NO atomics, no accumulator buffer, no zeroing, no separate
// dropout pass). Per 16-record chunk: coalesced int2 load, per-half ballot,
// extract up to 4 kept edges, 4 independent float4 gathers batched (MLP=4).
// All syncs use the half's 16-lane mask so divergent halves stay legal.
// ---------------------------------------------------------------------------
__global__ void spmm_csr_kernel(const float* __restrict__ src,   // = out + hop*64
                                const float* __restrict__ mrand,
                                float* __restrict__ out,
                                int hop) {
    const int lane = threadIdx.x & 31;
    const int l16  = lane & 15;
    const bool hi  = lane >= 16;
    const unsigned hmask = hi ? 0xFFFF0000u : 0x0000FFFFu;
    const int hbase = hi ? 16 : 0;
    const int gh = (blockIdx.x * blockDim.x + threadIdx.x) >> 4;  // global half id
    const int nh = (gridDim.x * blockDim.x) >> 4;
    const int hopbit = 1 << (18 + hop);
    const float sc = 1.0f / 0.9f;

    for (int r = gh; r < NN; r += nh) {
        const int s = __ldg(&g_start[r]);
        const int n = __ldg(&g_cnt[r]);
        float4 acc = make_float4(0.f, 0.f, 0.f, 0.f);
        for (int b = 0; b < n; b += 16) {
            int i = b + l16;
            int2 ed = (i < n) ? __ldcs(&g_edges[s + i]) : make_int2(0, 0);
            bool keep = (i < n) && (ed.x & hopbit);
            unsigned bm = __ballot_sync(hmask, keep);
            bm = hi ? (bm >> 16) : (bm & 0xFFFFu);
            while (bm) {
                int j0 = __ffs(bm) - 1;             bm &= bm - 1;
                int j1 = bm ? __ffs(bm) - 1 : -1;   bm &= bm - 1;
                int j2 = bm ? __ffs(bm) - 1 : -1;   bm &= bm - 1;
                int j3 = bm ? __ffs(bm) - 1 : -1;   bm &= bm - 1;
                bool a1 = j1 >= 0, a2 = j2 >= 0, a3 = j3 >= 0;
                int s0 = j0 + hbase;
                int s1 = (a1 ? j1 : j0) + hbase;
                int s2 = (a2 ? j2 : j0) + hbase;
                int s3 = (a3 ? j3 : j0) + hbase;
                int   c0 = __shfl_sync(hmask, ed.x, s0);
                float v0 = __int_as_float(__shfl_sync(hmask, ed.y, s0));
                int   c1 = __shfl_sync(hmask, ed.x, s1);
                float v1 = __int_as_float(__shfl_sync(hmask, ed.y, s1));
                int   c2 = __shfl_sync(hmask, ed.x, s2);
                float v2 = __int_as_float(__shfl_sync(hmask, ed.y, s2));
                int   c3 = __shfl_sync(hmask, ed.x, s3);
                float v3 = __int_as_float(__shfl_sync(hmask, ed.y, s3));
                c0 &= 0x3FFFF; c1 &= 0x3FFFF; c2 &= 0x3FFFF; c3 &= 0x3FFFF;
                float4 x0, x1, x2, x3;
                x0 = __ldg((const float4*)(src + (size_t)c0 * 256) + l16);
                if (a1) x1 = __ldg((const float4*)(src + (size_t)c1 * 256) + l16);
                if (a2) x2 = __ldg((const float4*)(src + (size_t)c2 * 256) + l16);
                if (a3) x3 = __ldg((const float4*)(src + (size_t)c3 * 256) + l16);
                acc.x += v0 * x0.x; acc.y += v0 * x0.y;
                acc.z += v0 * x0.z; acc.w += v0 * x0.w;
                if (a1) { acc.x += v1 * x1.x; acc.y += v1 * x1.y;
                          acc.z += v1 * x1.z; acc.w += v1 * x1.w; }
                if (a2) { acc.x += v2 * x2.x; acc.y += v2 * x2.y;
                          acc.z += v2 * x2.z; acc.w += v2 * x2.w; }
                if (a3) { acc.x += v3 * x3.x; acc.y += v3 * x3.y;
                          acc.z += v3 * x3.z; acc.w += v3 * x3.w; }
            }
        }
        // fused message dropout + write next hop slice (sole owner of row r)
        float4 m = __ldcs((const float4*)(mrand + (size_t)r * 64) + l16);
        acc.x = (m.x >= 0.1f) ? acc.x * sc : 0.f;
        acc.y = (m.y >= 0.1f) ? acc.y * sc : 0.f;
        acc.z = (m.z >= 0.1f) ? acc.z * sc : 0.f;
        acc.w = (m.w >= 0.1f) ? acc.w * sc : 0.f;
        ((float4*)(out + (size_t)r * 256 + (size_t)(hop + 1) * 64))[l16] = acc;
    }
}

// ---------------------------------------------------------------------------
extern "C" void kernel_launch(void* const* d_in, const int* in_sizes, int n_in,
                              void* d_out, int out_size) {
    const float* user  = (const float*)d_in[0];
    const float* item  = (const float*)d_in[1];
    const int*   rows  = (const int*)  d_in[2];
    const int*   cols  = (const int*)  d_in[3];
    const float* vals  = (const float*)d_in[4];
    const float* erand = (const float*)d_in[5];
    const float* mrand = (const float*)d_in[6];
    float*       out   = (float*)d_out;

    const int totalT    = NN * D / 16;      // 600,000
    const int ewThreads = 256;
    const int ewBlocks  = (totalT + ewThreads - 1) / ewThreads;

    const int gsBlocks  = 148 * 32;
    const int gsThreads = 256;

    // Launches: 0 init, 1 hist, 2 scan, 3 scatter, 4 spmm0, 5 spmm1, 6 spmm2
    // (ncu -s 5 -c 1 -> profiles spmm_csr hop 1)
    init_kernel<<<ewBlocks, ewThreads>>>(user, item, out);
    hist_kernel<<<gsBlocks, gsThreads>>>(rows);
    scan_kernel<<<1, 1024>>>();
    scatter_kernel<<<gsBlocks, gsThreads>>>(rows, cols, vals, erand);
    for (int hop = 0; hop < HOPS; ++hop) {
        spmm_csr_kernel<<<gsBlocks, gsThreads>>>(out + (size_t)hop * 64,
                                                 mrand + (size_t)hop * NN * D,
                                                 out, hop);
    }
}

// round 15
// speedup vs baseline: 1.3649x; 1.3649x over previous
#include <cuda_runtime.h>
#include <cstdint>

#define NU    100000
#define NI    50000
#define NN    150000            // NU + NI
#define D     64
#define NNZ_  8000000
#define HOPS  3
#define CAP   160               // padded row capacity; P(Poisson(53)>160) ~ 0

// Static device scratch (per harness rules: no allocations).
__device__ int  g_cnt[NN];                      // per-row edge count
__device__ int2 g_edges[(size_t)NN * CAP];      // padded rows: {col|mask<<18, val*2}

// ---------------------------------------------------------------------------
// Dummy: shifts launch indices so ncu (-s 5 -c 1) profiles hop 2.
// ---------------------------------------------------------------------------
__global__ void dummy_kernel() {
    if (threadIdx.x == 0 && blockIdx.x == 0) g_cnt[0] = 0;   // overwritten by init
}

// ---------------------------------------------------------------------------
// Init: out[:, 0, :] = concat(user, item); zero row counters.
// ---------------------------------------------------------------------------
__global__ void init_kernel(const float* __restrict__ user,
                            const float* __restrict__ item,
                            float* __restrict__ out) {
    int t = blockIdx.x * blockDim.x + threadIdx.x;
    if (t < NN) g_cnt[t] = 0;
    const int total = NN * D / 16;          // 600,000 threads
    if (t >= total) return;
    const int base   = t * 4;
    const int userF4 = NU * D / 4;
    float4 v[4];
    #pragma unroll
    for (int i = 0; i < 4; ++i) {
        int idx = base + i;
        v[i] = (idx < userF4) ? ((const float4*)user)[idx]
                              : ((const float4*)item)[idx - userF4];
    }
    const int node = base >> 4;
    const int f4   = base & 15;
    #pragma unroll
    for (int i = 0; i < 4; ++i)
        ((float4*)out)[(size_t)node * 64 + f4 + i] = v[i];
}

// ---------------------------------------------------------------------------
// ONE-PASS build (no hist, no scan): pos = row*CAP + atomicAdd(cnt[row]).
// 4 independent chains per thread to hide atomic+scattered-store latency.
// Record packs {col | keepmask<<18, val*2} (col < 2^18).
// ---------------------------------------------------------------------------
__global__ void build_kernel(const int*   __restrict__ rows,
                             const int*   __restrict__ cols,
                             const float* __restrict__ vals,
                             const float* __restrict__ erand) {
    int t  = blockIdx.x * blockDim.x + threadIdx.x;
    int nt = gridDim.x * blockDim.x;
    for (int base = t; base < NNZ_; base += 4 * nt) {
        int  e[4]; bool g[4]; int r[4]; int2 rec[4];
        #pragma unroll
        for (int k = 0; k < 4; ++k) { e[k] = base + k * nt; g[k] = e[k] < NNZ_; }
        #pragma unroll
        for (int k = 0; k < 4; ++k) {
            if (g[k]) {
                int   ee = e[k];
                r[k]     = __ldcs(rows + ee);
                int   c  = __ldcs(cols + ee);
                float v  = __ldcs(vals + ee) * 2.0f;    // 1/(1-0.5)
                int m = (__ldcs(erand + ee)            >= 0.5f ? 1 : 0)
                      | (__ldcs(erand + NNZ_ + ee)     >= 0.5f ? 2 : 0)
                      | (__ldcs(erand + 2 * NNZ_ + ee) >= 0.5f ? 4 : 0);
                rec[k] = make_int2(c | (m << 18), __float_as_int(v));
            }
        }
        int p[4];
        #pragma unroll
        for (int k = 0; k < 4; ++k)
            if (g[k]) p[k] = atomicAdd(&g_cnt[r[k]], 1);
        #pragma unroll
        for (int k = 0; k < 4; ++k)
            if (g[k]) __stcs(&g_edges[(size_t)r[k] * CAP + p[k]],
                             *(const int2*)&rec[k]);
    }
}

// ---------------------------------------------------------------------------
// Padded-CSR SpMM + fused message dropout. FULL WARP PER ROW:
// float2/lane covers D=64. Per 32-record chunk: coalesced int2 load, ballot,
// extract up to 8 kept edges, 8 independent full-warp float2 gathers batched
// per lane (MLP=8) before the FMAs. Row owned by one warp -> no atomics, no
// accumulator buffer, no separate dropout pass.
// ---------------------------------------------------------------------------
__global__ void spmm_ell_kernel(const float* __restrict__ src,   // = out + hop*64
                                const float* __restrict__ mrand, // hop slice
                                float* __restrict__ out,
                                int hop) {
    const int lane = threadIdx.x & 31;
    const int gw   = (blockIdx.x * blockDim.x + threadIdx.x) >> 5;
    const int nw   = (gridDim.x * blockDim.x) >> 5;
    const int hopbit = 1 << (18 + hop);
    const float sc = 1.0f / 0.9f;

    for (int r = gw; r < NN; r += nw) {
        const int n = __ldg(&g_cnt[r]);
        const int2* __restrict__ ebase = g_edges + (size_t)r * CAP;
        float accx = 0.f, accy = 0.f;
        for (int b = 0; b < n; b += 32) {
            int i = b + lane;
            int2 ed = (i < n) ? __ldcs(ebase + i) : make_int2(0, 0);
            bool keep = (i < n) && (ed.x & hopbit);
            unsigned mask = __ballot_sync(0xFFFFFFFFu, keep);
            while (mask) {
                int l[8];
                #pragma unroll
                for (int k = 0; k < 8; ++k) {
                    l[k] = mask ? (__ffs(mask) - 1) : 32;
                    mask &= mask - 1;
                }
                int   c[8]; float v[8]; bool a[8];
                #pragma unroll
                for (int k = 0; k < 8; ++k) {
                    a[k] = l[k] < 32;
                    int s = a[k] ? l[k] : 0;
                    c[k] = __shfl_sync(0xFFFFFFFFu, ed.x, s) & 0x3FFFF;
                    v[k] = __int_as_float(__shfl_sync(0xFFFFFFFFu, ed.y, s));
                }
                float2 x[8];
                #pragma unroll
                for (int k = 0; k < 8; ++k)
                    if (a[k]) x[k] = __ldg((const float2*)(src + (size_t)c[k] * 256) + lane);
                #pragma unroll
                for (int k = 0; k < 8; ++k)
                    if (a[k]) { accx += v[k] * x[k].x; accy += v[k] * x[k].y; }
            }
        }
        // fused message dropout + write next hop slice (sole owner of row r)
        float2 m = __ldcs((const float2*)(mrand + (size_t)r * 64) + lane);
        float2 o;
        o.x = (m.x >= 0.1f) ? accx * sc : 0.f;
        o.y = (m.y >= 0.1f) ? accy * sc : 0.f;
        ((float2*)(out + (size_t)r * 256 + (size_t)(hop + 1) * 64))[lane] = o;
    }
}

// ---------------------------------------------------------------------------
extern "C" void kernel_launch(void* const* d_in, const int* in_sizes, int n_in,
                              void* d_out, int out_size) {
    const float* user  = (const float*)d_in[0];
    const float* item  = (const float*)d_in[1];
    const int*   rows  = (const int*)  d_in[2];
    const int*   cols  = (const int*)  d_in[3];
    const float* vals  = (const float*)d_in[4];
    const float* erand = (const float*)d_in[5];
    const float* mrand = (const float*)d_in[6];
    float*       out   = (float*)d_out;

    const int totalT    = NN * D / 16;      // 600,000
    const int ewThreads = 256;
    const int ewBlocks  = (totalT + ewThreads - 1) / ewThreads;

    const int gsBlocks  = 148 * 32;
    const int gsThreads = 256;

    // Launches: 0 dummy, 1 init, 2 build, 3 hop0, 4 hop1, 5 hop2
    // (ncu -s 5 -c 1 -> profiles spmm_ell hop 2)
    dummy_kernel<<<1, 32>>>();
    init_kernel<<<ewBlocks, ewThreads>>>(user, item, out);
    build_kernel<<<gsBlocks, gsThreads>>>(rows, cols, vals, erand);
    for (int hop = 0; hop < HOPS; ++hop) {
        spmm_ell_kernel<<<gsBlocks, gsThreads>>>(out + (size_t)hop * 64,
                                                 mrand + (size_t)hop * NN * D,
                                                 out, hop);
    }
}